// round 1
// baseline (speedup 1.0000x reference)
#include <cuda_runtime.h>

// FullPairwise (non-PBC): output layout (float32), MP = M*P:
//   [0      , 2*MP) : atom_index12   out[r*MP + m*P + p] = (r? j : i) + m*N
//   [2*MP   , 5*MP) : shift_values   zeros, element (m*P+p, c) at 2*MP + (m*P+p)*3 + c
//   [5*MP   , 6*MP) : mask           1.0f if d2 <= 5.2^2 else 0.0f
static constexpr int       NA = 2048;
static constexpr int       NM = 4;
static constexpr long long PP = (long long)NA * (NA - 1) / 2;  // 2,096,128

__device__ __forceinline__ long long cumrow(int i) {
    // number of upper-tri (k=1) pairs with first index < i
    return (long long)i * (NA - 1) - (long long)i * (i - 1) / 2;
}

__global__ void __launch_bounds__(256)
fullpair_kernel(const float* __restrict__ coords,  // [NM, NA, 3]
                float* __restrict__ out)
{
    const long long P  = PP;
    const long long MP = (long long)NM * P;

    const long long p0 = ((long long)blockIdx.x * blockDim.x + threadIdx.x) * 4;
    if (p0 >= P) return;

    // Invert triangular index: largest i with cumrow(i) <= p0
    double disc = (double)(2 * NA - 1) * (2 * NA - 1) - 8.0 * (double)p0;
    int i = (int)(((double)(2 * NA - 1) - sqrt(disc)) * 0.5);
    if (i < 0) i = 0;
    if (i > NA - 2) i = NA - 2;
    while (cumrow(i + 1) <= p0) ++i;
    while (cumrow(i) > p0) --i;
    int j = (int)(p0 - cumrow(i)) + i + 1;

    const float c2 = 5.2f * 5.2f;  // folded in fp32, matches jnp f32 square

    float iv[4], jv[4];
    float mk[NM][4];
    float cix[NM], ciy[NM], ciz[NM];
    int cached_i = -1;

    int ii = i, jj = j;
    #pragma unroll
    for (int k = 0; k < 4; ++k) {
        iv[k] = (float)ii;
        jv[k] = (float)jj;
        if (ii != cached_i) {
            #pragma unroll
            for (int m = 0; m < NM; ++m) {
                const float* ci = coords + ((long long)m * NA + ii) * 3;
                cix[m] = ci[0]; ciy[m] = ci[1]; ciz[m] = ci[2];
            }
            cached_i = ii;
        }
        #pragma unroll
        for (int m = 0; m < NM; ++m) {
            const float* cj = coords + ((long long)m * NA + jj) * 3;
            float dx = __fsub_rn(cix[m], cj[0]);
            float dy = __fsub_rn(ciy[m], cj[1]);
            float dz = __fsub_rn(ciz[m], cj[2]);
            // same association order as jnp.sum over axis -1: (x+y)+z, no fma
            float d2 = __fadd_rn(__fadd_rn(__fmul_rn(dx, dx), __fmul_rn(dy, dy)),
                                 __fmul_rn(dz, dz));
            mk[m][k] = (d2 <= c2) ? 1.0f : 0.0f;
        }
        ++jj;
        if (jj >= NA) { ++ii; jj = ii + 1; }
    }

    const float4 z4 = make_float4(0.f, 0.f, 0.f, 0.f);
    #pragma unroll
    for (int m = 0; m < NM; ++m) {
        const float off = (float)(m * NA);
        float4 vi = make_float4(iv[0] + off, iv[1] + off, iv[2] + off, iv[3] + off);
        float4 vj = make_float4(jv[0] + off, jv[1] + off, jv[2] + off, jv[3] + off);
        *(float4*)(out + (long long)m * P + p0)      = vi;   // atom_index12 row 0
        *(float4*)(out + MP + (long long)m * P + p0) = vj;   // atom_index12 row 1

        float* sbase = out + 2 * MP + ((long long)m * P + p0) * 3;  // 12 zero floats
        ((float4*)sbase)[0] = z4;
        ((float4*)sbase)[1] = z4;
        ((float4*)sbase)[2] = z4;

        *(float4*)(out + 5 * MP + (long long)m * P + p0) =
            make_float4(mk[m][0], mk[m][1], mk[m][2], mk[m][3]);   // mask
    }
}

extern "C" void kernel_launch(void* const* d_in, const int* in_sizes, int n_in,
                              void* d_out, int out_size) {
    // inputs per metadata order: species(int32), coordinates(f32), cell(f32), pbc(bool)
    const float* coords = (const float*)d_in[1];
    float* out = (float*)d_out;

    const long long nthreads = PP / 4;                  // 524,032
    const int threads = 256;
    const int blocks = (int)((nthreads + threads - 1) / threads);  // 2047
    fullpair_kernel<<<blocks, threads>>>(coords, out);
}

// round 2
// speedup vs baseline: 1.4437x; 1.4437x over previous
#include <cuda_runtime.h>

// FullPairwise (non-PBC): output layout (float32), MP = M*P:
//   [0      , 2*MP) : atom_index12   out[r*MP + m*P + p] = (r? j : i) + m*N
//   [2*MP   , 5*MP) : shift_values   zeros (flat region, filled coalesced)
//   [5*MP   , 6*MP) : mask           1.0f if d2 <= 5.2^2 else 0.0f
static constexpr int       NA = 2048;
static constexpr int       NM = 4;
static constexpr long long PP = (long long)NA * (NA - 1) / 2;  // 2,096,128
static constexpr long long MP = (long long)NM * PP;            // 8,384,512

static constexpr int  THREADS     = 256;
static constexpr long long PAIR_THREADS = PP / 4;                      // 524,032
static constexpr int  PAIR_BLOCKS = (int)((PAIR_THREADS + THREADS - 1) / THREADS);  // 2047
static constexpr long long ZERO_F4 = 3 * MP / 4;                       // 6,288,384 float4
static constexpr int  ZERO_BLOCKS = (int)((ZERO_F4 + THREADS - 1) / THREADS);       // 24,564

__device__ __forceinline__ long long cumrow(int i) {
    return (long long)i * (NA - 1) - (long long)i * (i - 1) / 2;
}

__global__ void __launch_bounds__(256)
fullpair_kernel(const float* __restrict__ coords,  // [NM, NA, 3]
                float* __restrict__ out)
{
    // ---- suffix blocks: coalesced zero-fill of shift_values region ----
    if (blockIdx.x >= PAIR_BLOCKS) {
        long long q = (long long)(blockIdx.x - PAIR_BLOCKS) * blockDim.x + threadIdx.x;
        if (q < ZERO_F4) {
            __stcs((float4*)(out + 2 * MP) + q, make_float4(0.f, 0.f, 0.f, 0.f));
        }
        return;
    }

    // ---- prefix blocks: pair indices + mask ----
    const long long p0 = ((long long)blockIdx.x * blockDim.x + threadIdx.x) * 4;
    if (p0 >= PP) return;

    // Invert triangular index: largest i with cumrow(i) <= p0
    double disc = (double)(2 * NA - 1) * (2 * NA - 1) - 8.0 * (double)p0;
    int i = (int)(((double)(2 * NA - 1) - sqrt(disc)) * 0.5);
    if (i < 0) i = 0;
    if (i > NA - 2) i = NA - 2;
    while (cumrow(i + 1) <= p0) ++i;
    while (cumrow(i) > p0) --i;
    int j = (int)(p0 - cumrow(i)) + i + 1;

    const float c2 = 5.2f * 5.2f;

    float iv[4], jv[4];
    float mk[NM][4];
    float cix[NM], ciy[NM], ciz[NM];
    int cached_i = -1;

    int ii = i, jj = j;
    #pragma unroll
    for (int k = 0; k < 4; ++k) {
        iv[k] = (float)ii;
        jv[k] = (float)jj;
        if (ii != cached_i) {
            #pragma unroll
            for (int m = 0; m < NM; ++m) {
                const float* ci = coords + ((long long)m * NA + ii) * 3;
                cix[m] = ci[0]; ciy[m] = ci[1]; ciz[m] = ci[2];
            }
            cached_i = ii;
        }
        #pragma unroll
        for (int m = 0; m < NM; ++m) {
            const float* cj = coords + ((long long)m * NA + jj) * 3;
            float dx = __fsub_rn(cix[m], cj[0]);
            float dy = __fsub_rn(ciy[m], cj[1]);
            float dz = __fsub_rn(ciz[m], cj[2]);
            // same association order as jnp.sum over axis -1: (x+y)+z, no fma
            float d2 = __fadd_rn(__fadd_rn(__fmul_rn(dx, dx), __fmul_rn(dy, dy)),
                                 __fmul_rn(dz, dz));
            mk[m][k] = (d2 <= c2) ? 1.0f : 0.0f;
        }
        ++jj;
        if (jj >= NA) { ++ii; jj = ii + 1; }
    }

    #pragma unroll
    for (int m = 0; m < NM; ++m) {
        const float off = (float)(m * NA);
        float4 vi = make_float4(iv[0] + off, iv[1] + off, iv[2] + off, iv[3] + off);
        float4 vj = make_float4(jv[0] + off, jv[1] + off, jv[2] + off, jv[3] + off);
        __stcs((float4*)(out + (long long)m * PP + p0), vi);        // index row 0
        __stcs((float4*)(out + MP + (long long)m * PP + p0), vj);   // index row 1
        __stcs((float4*)(out + 5 * MP + (long long)m * PP + p0),
               make_float4(mk[m][0], mk[m][1], mk[m][2], mk[m][3])); // mask
    }
}

extern "C" void kernel_launch(void* const* d_in, const int* in_sizes, int n_in,
                              void* d_out, int out_size) {
    // inputs per metadata order: species(int32), coordinates(f32), cell(f32), pbc(bool)
    const float* coords = (const float*)d_in[1];
    float* out = (float*)d_out;

    fullpair_kernel<<<PAIR_BLOCKS + ZERO_BLOCKS, THREADS>>>(coords, out);
}

// round 3
// speedup vs baseline: 1.5923x; 1.1030x over previous
#include <cuda_runtime.h>

// FullPairwise (non-PBC): output layout (float32), MP = M*P:
//   [0      , 2*MP) : atom_index12   out[r*MP + m*P + p] = (r? j : i) + m*N
//   [2*MP   , 5*MP) : shift_values   zeros (flat region, filled coalesced)
//   [5*MP   , 6*MP) : mask           1.0f if d2 <= 5.2^2 else 0.0f
static constexpr int       NA = 2048;
static constexpr int       NM = 4;
static constexpr long long PP = (long long)NA * (NA - 1) / 2;  // 2,096,128
static constexpr long long MP = (long long)NM * PP;            // 8,384,512

static constexpr int  THREADS      = 256;
static constexpr long long QUADS   = PP / 4;                                        // 524,032
static constexpr int  PAIR_BLOCKS  = (int)((QUADS + THREADS - 1) / THREADS);        // 2047
static constexpr long long ZERO_F4 = 3 * MP / 4;                                    // 6,288,384
static constexpr int  ZERO_BLOCKS  = (int)((ZERO_F4 + THREADS - 1) / THREADS);      // 24,564

__device__ __forceinline__ long long cumrow(int i) {
    return (long long)i * (NA - 1) - (long long)i * (i - 1) / 2;
}

__global__ void __launch_bounds__(256)
fullpair_kernel(const float* __restrict__ coords,  // [NM, NA, 3]
                float* __restrict__ out)
{
    // ---- suffix blocks: coalesced zero-fill of shift_values region ----
    if (blockIdx.x >= NM * PAIR_BLOCKS) {
        long long q = (long long)(blockIdx.x - NM * PAIR_BLOCKS) * blockDim.x + threadIdx.x;
        if (q < ZERO_F4) {
            __stcs((float4*)(out + 2 * MP) + q, make_float4(0.f, 0.f, 0.f, 0.f));
        }
        return;
    }

    // ---- pair blocks: one thread = 4 consecutive pairs of ONE molecule ----
    const int m  = blockIdx.x / PAIR_BLOCKS;
    const int pb = blockIdx.x - m * PAIR_BLOCKS;
    const long long p0 = ((long long)pb * blockDim.x + threadIdx.x) * 4;
    if (p0 >= PP) return;

    // Invert triangular index in fp32 (all values < 2^24, exact), then
    // correct exactly with integer loops.
    float disc = (float)((long long)(2 * NA - 1) * (2 * NA - 1) - 8 * p0);  // exact
    int i = (int)(((float)(2 * NA - 1) - sqrtf(disc)) * 0.5f);
    if (i < 0) i = 0;
    if (i > NA - 2) i = NA - 2;
    while (cumrow(i + 1) <= p0) ++i;
    while (cumrow(i) > p0) --i;
    int j = (int)(p0 - cumrow(i)) + i + 1;

    const float c2 = 5.2f * 5.2f;
    const float off = (float)(m * NA);
    const float* __restrict__ cm = coords + (long long)m * NA * 3;

    float iv[4], jv[4], mk[4];
    float cix = 0.f, ciy = 0.f, ciz = 0.f;
    int cached_i = -1;

    int ii = i, jj = j;
    #pragma unroll
    for (int k = 0; k < 4; ++k) {
        iv[k] = (float)ii + off;
        jv[k] = (float)jj + off;
        if (ii != cached_i) {
            const float* ci = cm + ii * 3;
            cix = ci[0]; ciy = ci[1]; ciz = ci[2];
            cached_i = ii;
        }
        const float* cj = cm + jj * 3;
        float dx = __fsub_rn(cix, cj[0]);
        float dy = __fsub_rn(ciy, cj[1]);
        float dz = __fsub_rn(ciz, cj[2]);
        // same association order as jnp.sum over axis -1: (x+y)+z, no fma
        float d2 = __fadd_rn(__fadd_rn(__fmul_rn(dx, dx), __fmul_rn(dy, dy)),
                             __fmul_rn(dz, dz));
        mk[k] = (d2 <= c2) ? 1.0f : 0.0f;
        ++jj;
        if (jj >= NA) { ++ii; jj = ii + 1; }
    }

    __stcs((float4*)(out + (long long)m * PP + p0),
           make_float4(iv[0], iv[1], iv[2], iv[3]));                 // index row 0
    __stcs((float4*)(out + MP + (long long)m * PP + p0),
           make_float4(jv[0], jv[1], jv[2], jv[3]));                 // index row 1
    __stcs((float4*)(out + 5 * MP + (long long)m * PP + p0),
           make_float4(mk[0], mk[1], mk[2], mk[3]));                 // mask
}

extern "C" void kernel_launch(void* const* d_in, const int* in_sizes, int n_in,
                              void* d_out, int out_size) {
    // inputs per metadata order: species(int32), coordinates(f32), cell(f32), pbc(bool)
    const float* coords = (const float*)d_in[1];
    float* out = (float*)d_out;

    fullpair_kernel<<<NM * PAIR_BLOCKS + ZERO_BLOCKS, THREADS>>>(coords, out);
}